// round 6
// baseline (speedup 1.0000x reference)
#include <cuda_runtime.h>

// DilatedReparamBlock == single 13x13 depthwise conv + per-channel bias.
//
// R5: f32x2 FMA with (a) 4 output rows/thread to cut smem traffic per FMA,
// (b) SSTR=70 for conflict-free 8B-bank access, (c) peeled edge rows so no
// zero-weight FMA waste. Shifted second tile (sx2) still supplies odd-kx
// pairs as direct aligned LDS64 — zero ALU repacking.

#define CC 256
#define HW 56
#define PAD 6
#define SROWS 68            // 56 + 2*6
#define SSTR  70            // floats/row: quad-stride 140≡12, colb 7 (mod16) -> conflict-free
#define NTHR 64

typedef unsigned long long u64;

__device__ u64   g_wdup[CC * 169];   // (w,w) duplicated pairs, 13x13
__device__ float g_bias[CC];

static __device__ __forceinline__ void ffma2(u64& acc, u64 x2, u64 w2)
{
    asm("fma.rn.f32x2 %0, %1, %2, %0;" : "+l"(acc) : "l"(x2), "l"(w2));
}

__global__ void prep_kernel(const float* __restrict__ lk_w,
                            const float* __restrict__ w0, const float* __restrict__ w1,
                            const float* __restrict__ w2, const float* __restrict__ w3,
                            const float* __restrict__ w4, const float* __restrict__ w5,
                            const float* __restrict__ gamma, const float* __restrict__ beta,
                            const float* __restrict__ mean,  const float* __restrict__ var)
{
    int c = blockIdx.x;
    int t = threadIdx.x;

    float s[7], sh[7];
#pragma unroll
    for (int i = 0; i < 7; i++) {
        float sc = gamma[i * CC + c] * rsqrtf(var[i * CC + c] + 1e-5f);
        s[i]  = sc;
        sh[i] = beta[i * CC + c] - mean[i * CC + c] * sc;
    }
    if (t == 0)
        g_bias[c] = sh[0] + sh[1] + sh[2] + sh[3] + sh[4] + sh[5] + sh[6];

    if (t < 169) {
        int ty = t / 13, tx = t % 13;
        int dy = ty - PAD, dx = tx - PAD;
        float acc = s[0] * lk_w[c * 169 + t];

        const float* ws[6]   = { w0, w1, w2, w3, w4, w5 };
        const int    KSa[6]  = { 5, 7, 7, 3, 3, 3 };
        const int    DILa[6] = { 1, 1, 2, 3, 4, 5 };
#pragma unroll
        for (int j = 0; j < 6; j++) {
            int r = DILa[j], k = KSa[j];
            if (dy % r == 0 && dx % r == 0) {
                int a  = dy / r + (k - 1) / 2;
                int b2 = dx / r + (k - 1) / 2;
                if (a >= 0 && a < k && b2 >= 0 && b2 < k)
                    acc += s[j + 1] * ws[j][c * k * k + a * k + b2];
            }
        }
        unsigned int u = __float_as_uint(acc);
        g_wdup[c * 169 + t] = (u64)u | ((u64)u << 32);
    }
}

// One input row: accumulate into output rows JLO..JHI (weight row = iy - j).
template<int JLO, int JHI>
static __device__ __forceinline__ void row_pass(const u64* __restrict__ er,
                                                const u64* __restrict__ sr,
                                                const u64* __restrict__ swd,
                                                int iy, u64 acc[4][7])
{
    u64 xe[13], xo[12];
#pragma unroll
    for (int i = 0; i < 13; i++) xe[i] = er[i];
#pragma unroll
    for (int i = 0; i < 12; i++) xo[i] = sr[i];

#pragma unroll
    for (int kx = 0; kx < 13; kx++) {
        u64 w[4];
#pragma unroll
        for (int j = JLO; j <= JHI; j++) w[j] = swd[(iy - j) * 13 + kx];
#pragma unroll
        for (int p = 0; p < 7; p++) {
            u64 x2 = (kx & 1) ? xo[((kx - 1) >> 1) + p] : xe[(kx >> 1) + p];
#pragma unroll
            for (int j = JLO; j <= JHI; j++) ffma2(acc[j][p], x2, w[j]);
        }
    }
}

__global__ void __launch_bounds__(NTHR, 5) conv_kernel(const float* __restrict__ x,
                                                       float* __restrict__ out)
{
    __shared__ float sx [SROWS * SSTR];   // X(r,c)   19040 B
    __shared__ float sx2[SROWS * SSTR];   // X(r,c+1) 19040 B
    __shared__ u64   swd[169];            // 1352 B
    __shared__ float sbias;

    int bc = blockIdx.x;
    const float* xim = x   + (size_t)bc * (HW * HW);
    float*       oim = out + (size_t)bc * (HW * HW);
    int tid = threadIdx.x;
    int c   = bc & (CC - 1);

    // Fill both padded tiles (zero halo), coalesced.
    for (int idx = tid; idx < SROWS * SROWS; idx += NTHR) {
        int r   = idx / SROWS;
        int cc2 = idx - r * SROWS;
        int iy = r - PAD, ix = cc2 - PAD;
        float v = 0.f, v2 = 0.f;
        if ((unsigned)iy < (unsigned)HW) {
            if ((unsigned)ix < (unsigned)HW)       v  = xim[iy * HW + ix];
            if ((unsigned)(ix + 1) < (unsigned)HW) v2 = xim[iy * HW + ix + 1];
        }
        sx [r * SSTR + cc2] = v;
        sx2[r * SSTR + cc2] = v2;
    }
    for (int t = tid; t < 169; t += NTHR) swd[t] = g_wdup[c * 169 + t];
    if (tid == 0) sbias = g_bias[c];
    __syncthreads();

    int colb = tid & 3;                 // ox0 = colb*14 (even -> aligned)
    int quad = tid >> 2;                // oy0 = quad*4, quad<14 active
    if (quad >= 14) return;
    int oy0 = quad * 4;
    int ox0 = colb * 14;

    u64 acc[4][7];
#pragma unroll
    for (int j = 0; j < 4; j++)
#pragma unroll
        for (int p = 0; p < 7; p++) acc[j][p] = 0ull;

#define ER(iy) reinterpret_cast<const u64*>(&sx [(oy0 + (iy)) * SSTR + ox0])
#define SR(iy) reinterpret_cast<const u64*>(&sx2[(oy0 + (iy)) * SSTR + ox0])

    // Peeled edges: output row j uses weight row iy-j (valid 0..12).
    row_pass<0, 0>(ER(0),  SR(0),  swd, 0,  acc);
    row_pass<0, 1>(ER(1),  SR(1),  swd, 1,  acc);
    row_pass<0, 2>(ER(2),  SR(2),  swd, 2,  acc);
#pragma unroll 1
    for (int iy = 3; iy <= 12; iy++)
        row_pass<0, 3>(ER(iy), SR(iy), swd, iy, acc);
    row_pass<1, 3>(ER(13), SR(13), swd, 13, acc);
    row_pass<2, 3>(ER(14), SR(14), swd, 14, acc);
    row_pass<3, 3>(ER(15), SR(15), swd, 15, acc);
#undef ER
#undef SR

    float bb = sbias;
#pragma unroll
    for (int j = 0; j < 4; j++) {
        float2* o = reinterpret_cast<float2*>(&oim[(oy0 + j) * HW + ox0]);
#pragma unroll
        for (int p = 0; p < 7; p++) {
            o[p] = make_float2(__uint_as_float((unsigned)acc[j][p]) + bb,
                               __uint_as_float((unsigned)(acc[j][p] >> 32)) + bb);
        }
    }
}

extern "C" void kernel_launch(void* const* d_in, const int* in_sizes, int n_in,
                              void* d_out, int out_size)
{
    const float* x    = (const float*)d_in[0];
    const float* lk_w = (const float*)d_in[1];
    const float* w0   = (const float*)d_in[2];
    const float* w1   = (const float*)d_in[3];
    const float* w2   = (const float*)d_in[4];
    const float* w3   = (const float*)d_in[5];
    const float* w4   = (const float*)d_in[6];
    const float* w5   = (const float*)d_in[7];
    const float* g    = (const float*)d_in[8];
    const float* b    = (const float*)d_in[9];
    const float* m    = (const float*)d_in[10];
    const float* v    = (const float*)d_in[11];
    float* out = (float*)d_out;

    prep_kernel<<<CC, 192>>>(lk_w, w0, w1, w2, w3, w4, w5, g, b, m, v);

    int nimg = out_size / (HW * HW);    // 8192
    conv_kernel<<<nimg, NTHR>>>(x, out);
}

// round 7
// speedup vs baseline: 1.8735x; 1.8735x over previous
#include <cuda_runtime.h>

// DilatedReparamBlock == single 13x13 depthwise conv + per-channel bias.
//
// R6: back to SCALAR FFMA (f32x2 shown FLOP-neutral on sm_100a; both prior
// builds were L1-bound). Kill the L1 bottleneck instead:
//  - conflict-free LDS128: lane map (colb = lane>>3, pair = warp*8+lane&7)
//    + 16B row swizzle shift(r) = 4*((r>>1)&7), SSTR = 96 (mult of 16).
//  - weight pairs (w[ky], w[ky-1]) as one LDS64 broadcast, 13 per row-iter.
//  - one smem tile only (no shifted copy), window = 7 aligned LDS128.
// Thread = 16-wide x 2 rows; edge row-iters peeled (no zero-weight FMAs).

#define CC 256
#define HW 56
#define PAD 6
#define SROWS 68            // 56 + 2*6
#define SSTR  96            // floats/row incl. swizzle head-room (68+28)
#define NTHR 128            // 4 warps; 112 active (28 row-pairs x 4 col-groups)

__device__ float  g_weq [CC * 169];       // folded 13x13 weights
__device__ float2 g_wpair[CC * 14 * 13];  // (w[iy][kx], w[iy-1][kx]); zeros at edges
__device__ float  g_bias[CC];

__global__ void prep_kernel(const float* __restrict__ lk_w,
                            const float* __restrict__ w0, const float* __restrict__ w1,
                            const float* __restrict__ w2, const float* __restrict__ w3,
                            const float* __restrict__ w4, const float* __restrict__ w5,
                            const float* __restrict__ gamma, const float* __restrict__ beta,
                            const float* __restrict__ mean,  const float* __restrict__ var)
{
    __shared__ float sweq[169];
    int c = blockIdx.x;
    int t = threadIdx.x;

    float s[7], sh[7];
#pragma unroll
    for (int i = 0; i < 7; i++) {
        float sc = gamma[i * CC + c] * rsqrtf(var[i * CC + c] + 1e-5f);
        s[i]  = sc;
        sh[i] = beta[i * CC + c] - mean[i * CC + c] * sc;
    }
    if (t == 0)
        g_bias[c] = sh[0] + sh[1] + sh[2] + sh[3] + sh[4] + sh[5] + sh[6];

    if (t < 169) {
        int ty = t / 13, tx = t % 13;
        int dy = ty - PAD, dx = tx - PAD;
        float acc = s[0] * lk_w[c * 169 + t];

        const float* ws[6]   = { w0, w1, w2, w3, w4, w5 };
        const int    KSa[6]  = { 5, 7, 7, 3, 3, 3 };
        const int    DILa[6] = { 1, 1, 2, 3, 4, 5 };
#pragma unroll
        for (int j = 0; j < 6; j++) {
            int r = DILa[j], k = KSa[j];
            if (dy % r == 0 && dx % r == 0) {
                int a  = dy / r + (k - 1) / 2;
                int b2 = dx / r + (k - 1) / 2;
                if (a >= 0 && a < k && b2 >= 0 && b2 < k)
                    acc += s[j + 1] * ws[j][c * k * k + a * k + b2];
            }
        }
        sweq[t] = acc;
        g_weq[c * 169 + t] = acc;
    }
    __syncthreads();

    if (t < 14 * 13) {
        int iy = t / 13, kx = t % 13;
        float hi = (iy < 13) ? sweq[iy * 13 + kx]       : 0.f;  // weight row iy
        float lo = (iy >= 1) ? sweq[(iy - 1) * 13 + kx] : 0.f;  // weight row iy-1
        g_wpair[c * 182 + t] = make_float2(hi, lo);
    }
}

// Accumulate one input row into rows {acc0 if DO0, acc1 if DO1}.
template<bool DO0, bool DO1>
static __device__ __forceinline__ void row_pass(const float* __restrict__ sx,
                                                const float2* __restrict__ swp,
                                                int rbase, int ox0, int iy,
                                                float acc0[16], float acc1[16])
{
    int r = rbase + iy;
    const float4* xr = reinterpret_cast<const float4*>(
        &sx[r * SSTR + ((((unsigned)r >> 1) & 7) << 2) + ox0]);
    float xw[28];
#pragma unroll
    for (int q = 0; q < 7; q++) {
        float4 v = xr[q];
        xw[q * 4 + 0] = v.x; xw[q * 4 + 1] = v.y;
        xw[q * 4 + 2] = v.z; xw[q * 4 + 3] = v.w;
    }
    const float2* wp = &swp[iy * 13];
#pragma unroll
    for (int kx = 0; kx < 13; kx++) {
        float2 w = wp[kx];
#pragma unroll
        for (int o = 0; o < 16; o++) {
            if (DO0) acc0[o] = fmaf(xw[kx + o], w.x, acc0[o]);
            if (DO1) acc1[o] = fmaf(xw[kx + o], w.y, acc1[o]);
        }
    }
}

__global__ void __launch_bounds__(NTHR, 4) conv_kernel(const float* __restrict__ x,
                                                       float* __restrict__ out)
{
    __shared__ float  sx[SROWS * SSTR];     // 26112 B, 16B-row-swizzled
    __shared__ float2 swp[14 * 13];         // 1456 B
    __shared__ float  sbias;

    int bc = blockIdx.x;
    const float* xim = x   + (size_t)bc * (HW * HW);
    float*       oim = out + (size_t)bc * (HW * HW);
    int tid = threadIdx.x;
    int c   = bc & (CC - 1);

    // Fill swizzled tile: physical slot p of row r holds logical col p-shift(r).
    for (int idx = tid; idx < SROWS * SSTR; idx += NTHR) {
        int r = idx / SSTR;
        int p = idx - r * SSTR;
        int shift = (((unsigned)r >> 1) & 7) << 2;
        int cl = p - shift;                  // logical padded col
        int iy = r - PAD, ix = cl - PAD;
        float v = 0.f;
        if ((unsigned)iy < (unsigned)HW && (unsigned)ix < (unsigned)HW)
            v = xim[iy * HW + ix];
        sx[idx] = v;
    }
    for (int t = tid; t < 182; t += NTHR) swp[t] = g_wpair[c * 182 + t];
    if (tid == 0) sbias = g_bias[c];
    __syncthreads();

    int warp = tid >> 5, lane = tid & 31;
    int colb = lane >> 3;                    // 0..3 -> ox0 = colb*16
    int pair = warp * 8 + (lane & 7);        // 0..31, active < 28
    if (pair >= 28) return;
    int oy0 = pair * 2;
    int ox0 = colb * 16;

    float acc0[16], acc1[16];
#pragma unroll
    for (int o = 0; o < 16; o++) { acc0[o] = 0.f; acc1[o] = 0.f; }

    // iy=0: only out row0 (w row -1 is zero). iy=13: only row1.
    row_pass<true, false>(sx, swp, oy0, ox0, 0, acc0, acc1);
#pragma unroll 1
    for (int iy = 1; iy <= 12; iy++)
        row_pass<true, true>(sx, swp, oy0, ox0, iy, acc0, acc1);
    row_pass<false, true>(sx, swp, oy0, ox0, 13, acc0, acc1);

    float bb = sbias;
    int nq = (colb == 3) ? 2 : 4;            // group 3: cols 48..55 only
    float4* o0 = reinterpret_cast<float4*>(&oim[oy0 * HW + ox0]);
    float4* o1 = reinterpret_cast<float4*>(&oim[(oy0 + 1) * HW + ox0]);
#pragma unroll
    for (int q = 0; q < 4; q++) {
        if (q < nq) {
            o0[q] = make_float4(acc0[q*4+0] + bb, acc0[q*4+1] + bb,
                                acc0[q*4+2] + bb, acc0[q*4+3] + bb);
            o1[q] = make_float4(acc1[q*4+0] + bb, acc1[q*4+1] + bb,
                                acc1[q*4+2] + bb, acc1[q*4+3] + bb);
        }
    }
}

extern "C" void kernel_launch(void* const* d_in, const int* in_sizes, int n_in,
                              void* d_out, int out_size)
{
    const float* x    = (const float*)d_in[0];
    const float* lk_w = (const float*)d_in[1];
    const float* w0   = (const float*)d_in[2];
    const float* w1   = (const float*)d_in[3];
    const float* w2   = (const float*)d_in[4];
    const float* w3   = (const float*)d_in[5];
    const float* w4   = (const float*)d_in[6];
    const float* w5   = (const float*)d_in[7];
    const float* g    = (const float*)d_in[8];
    const float* b    = (const float*)d_in[9];
    const float* m    = (const float*)d_in[10];
    const float* v    = (const float*)d_in[11];
    float* out = (float*)d_out;

    prep_kernel<<<CC, 192>>>(lk_w, w0, w1, w2, w3, w4, w5, g, b, m, v);

    int nimg = out_size / (HW * HW);    // 8192
    conv_kernel<<<nimg, NTHR>>>(x, out);
}